// round 14
// baseline (speedup 1.0000x reference)
#include <cuda_runtime.h>
#include <cuda_bf16.h>
#include <cuda_fp16.h>
#include <cstdint>

#define NN 100000
#define EE 1600000
#define DH 128
#define CC 64
#define NB_SCAN 98          // ceil(NN/1024)
#define KP 136              // bf16 row stride (272B) -> conflict-free ldmatrix

// ---------------- device scratch (static, no allocs) ----------------
__device__ __half   g_m1[(size_t)NN * DH];   // m buffers (fp16, ping-pong)
__device__ __half   g_m2[(size_t)NN * DH];
__device__ float    g_h[(size_t)NN * DH];    // layer-1 activations
__device__ float    g_dis[NN];               // deg^{-1/2}
__device__ unsigned g_deg[NN];               // 1 + in-degree
__device__ unsigned g_part[NN];              // scan partials
__device__ unsigned g_bsum[NB_SCAN];
__device__ unsigned g_off[NN + 1];           // CSR offsets
__device__ unsigned g_curs[NN];              // placement cursors
__device__ int2     g_edge[EE + 2];          // {src, bitcast(nrm)}
__device__ uint4    g_wf1[8 * 16 * 32];      // W mma B-fragments (hi,lo)
__device__ uint4    g_wf2[8 * 16 * 32];
__device__ uint4    g_wfl[8 * 8 * 32];
__device__ int      g_is64;

// ---------------- PTX helpers (plain sm_103-safe) ----------------
__device__ __forceinline__ uint32_t smem_u32(const void* p) {
    uint32_t a;
    asm("{ .reg .u64 t; cvta.to.shared.u64 t, %1; cvt.u32.u64 %0, t; }"
        : "=r"(a) : "l"(p));
    return a;
}
__device__ __forceinline__ void ldsm_x4(uint32_t* r, uint32_t addr) {
    asm volatile("ldmatrix.sync.aligned.m8n8.x4.shared.b16 {%0,%1,%2,%3}, [%4];"
                 : "=r"(r[0]), "=r"(r[1]), "=r"(r[2]), "=r"(r[3]) : "r"(addr));
}
__device__ __forceinline__ void mma_bf16(float* c, const uint32_t* a,
                                         const uint32_t* b) {
    asm volatile(
        "mma.sync.aligned.m16n8k16.row.col.f32.bf16.bf16.f32 "
        "{%0,%1,%2,%3}, {%4,%5,%6,%7}, {%8,%9}, {%0,%1,%2,%3};"
        : "+f"(c[0]), "+f"(c[1]), "+f"(c[2]), "+f"(c[3])
        : "r"(a[0]), "r"(a[1]), "r"(a[2]), "r"(a[3]), "r"(b[0]), "r"(b[1]));
}

// pack float4 -> hi bf16x2 pair + lo bf16x2 pair
__device__ __forceinline__ void split4(float4 v, uint2& hi, uint2& lo) {
    __nv_bfloat162 h01 = __floats2bfloat162_rn(v.x, v.y);
    __nv_bfloat162 h23 = __floats2bfloat162_rn(v.z, v.w);
    float lx = v.x - __bfloat162float(h01.x);
    float ly = v.y - __bfloat162float(h01.y);
    float lz = v.z - __bfloat162float(h23.x);
    float lw = v.w - __bfloat162float(h23.y);
    __nv_bfloat162 l01 = __floats2bfloat162_rn(lx, ly);
    __nv_bfloat162 l23 = __floats2bfloat162_rn(lz, lw);
    hi.x = *(uint32_t*)&h01; hi.y = *(uint32_t*)&h23;
    lo.x = *(uint32_t*)&l01; lo.y = *(uint32_t*)&l23;
}

// accumulate 8 fp16 cols (uint4) scaled by n into acc[8]
__device__ __forceinline__ void acc8(float* acc, uint4 v, float n) {
    float2 p0 = __half22float2(*(__half2*)&v.x);
    float2 p1 = __half22float2(*(__half2*)&v.y);
    float2 p2 = __half22float2(*(__half2*)&v.z);
    float2 p3 = __half22float2(*(__half2*)&v.w);
    acc[0] = fmaf(p0.x, n, acc[0]); acc[1] = fmaf(p0.y, n, acc[1]);
    acc[2] = fmaf(p1.x, n, acc[2]); acc[3] = fmaf(p1.y, n, acc[3]);
    acc[4] = fmaf(p2.x, n, acc[4]); acc[5] = fmaf(p2.y, n, acc[5]);
    acc[6] = fmaf(p3.x, n, acc[6]); acc[7] = fmaf(p3.y, n, acc[7]);
}

// ---------------- setup ----------------
__global__ void k_initdet(const int* __restrict__ w, unsigned* __restrict__ deg) {
    int i = blockIdx.x * blockDim.x + threadIdx.x;
    if (i < NN) deg[i] = 1u;                 // self-loop
    if (blockIdx.x == 0) {
        bool nz = (w[2 * threadIdx.x + 1] != 0);
        int any = __syncthreads_or((int)nz);
        if (threadIdx.x == 0) g_is64 = !any; // int64 vals < 2^31 -> odd words 0
    }
}
__global__ void k_deg(const void* __restrict__ ei, long long E,
                      unsigned* __restrict__ deg) {
    long long i = ((long long)blockIdx.x * blockDim.x + threadIdx.x) * 2;
    if (i >= E) return;
    int d0, d1 = -1;
    if (g_is64) {
        const long long* p = (const long long*)ei + E;
        if (i + 1 < E) {
            longlong2 v = *(const longlong2*)(p + i);
            d0 = (int)v.x; d1 = (int)v.y;
        } else d0 = (int)p[i];
    } else {
        const int* p = (const int*)ei + E;
        if (i + 1 < E) {
            int2 v = *(const int2*)(p + i);
            d0 = v.x; d1 = v.y;
        } else d0 = p[i];
    }
    atomicAdd(&deg[d0], 1u);
    if (d1 >= 0) atomicAdd(&deg[d1], 1u);
}

// precompute mma B-fragments for all three weight matrices
__global__ void k_wfrag(const float* __restrict__ W1, const float* __restrict__ W2,
                        const float* __restrict__ Wl,
                        uint4* __restrict__ f1, uint4* __restrict__ f2,
                        uint4* __restrict__ fl) {
    int i = blockIdx.x * blockDim.x + threadIdx.x;
    const float* W; uint4* F; int NT8, j;
    if (i < 4096)        { W = W1; F = f1; NT8 = 16; j = i; }
    else if (i < 8192)   { W = W2; F = f2; NT8 = 16; j = i - 4096; }
    else if (i < 10240)  { W = Wl; F = fl; NT8 = 8;  j = i - 8192; }
    else return;
    int lane = j & 31, t = j >> 5;
    int ni = t % NT8, ks = t / NT8;
    int n = ni * 8 + (lane >> 2);
    int k = ks * 16 + (lane & 3) * 2;
    const float* r = W + (size_t)n * 128;
    float w0 = r[k], w1 = r[k + 1], w2 = r[k + 8], w3 = r[k + 9];
    uint2 hi, lo;
    split4(make_float4(w0, w1, w2, w3), hi, lo);
    F[j] = make_uint4(hi.x, hi.y, lo.x, lo.y);    // {b0hi, b1hi, b0lo, b1lo}
}

// ---------------- CSR build ----------------
__global__ __launch_bounds__(1024) void k_scan1(const unsigned* __restrict__ deg,
                                                unsigned* __restrict__ part,
                                                unsigned* __restrict__ bsum) {
    __shared__ unsigned ws[32];
    int t = threadIdx.x;
    int i = blockIdx.x * 1024 + t;
    unsigned x = (i < NN) ? (deg[i] - 1u) : 0u;
    #pragma unroll
    for (int o = 1; o < 32; o <<= 1) {
        unsigned y = __shfl_up_sync(~0u, x, o);
        if ((t & 31) >= o) x += y;
    }
    if ((t & 31) == 31) ws[t >> 5] = x;
    __syncthreads();
    if (t < 32) {
        unsigned w = ws[t];
        #pragma unroll
        for (int o = 1; o < 32; o <<= 1) {
            unsigned y = __shfl_up_sync(~0u, w, o);
            if (t >= o) w += y;
        }
        ws[t] = w;
    }
    __syncthreads();
    if (t >= 32) x += ws[(t >> 5) - 1];
    if (i < NN) part[i] = x;
    if (t == 1023) bsum[blockIdx.x] = x;
}
__global__ void k_scan2(unsigned* __restrict__ bsum) {
    __shared__ unsigned s[NB_SCAN];
    int t = threadIdx.x;
    if (t < NB_SCAN) s[t] = bsum[t];
    __syncthreads();
    if (t == 0) {
        unsigned run = 0;
        for (int k = 0; k < NB_SCAN; k++) { unsigned v = s[k]; s[k] = run; run += v; }
    }
    __syncthreads();
    if (t < NB_SCAN) bsum[t] = s[t];
}
__global__ void k_scan3(const unsigned* __restrict__ deg,
                        const unsigned* __restrict__ part,
                        const unsigned* __restrict__ bsum,
                        unsigned* __restrict__ off, unsigned* __restrict__ curs,
                        float* __restrict__ dis, long long E) {
    int i = blockIdx.x * blockDim.x + threadIdx.x;
    if (i < NN) {
        unsigned dg = deg[i];
        unsigned incl = part[i] + bsum[i >> 10];
        unsigned excl = incl - (dg - 1u);
        off[i] = excl;
        curs[i] = excl;
        dis[i] = rsqrtf((float)dg);
    }
    if (i == 0) off[NN] = (unsigned)E;
}
__global__ void k_place(const void* __restrict__ ei, long long E,
                        const float* __restrict__ dis, unsigned* __restrict__ curs,
                        int2* __restrict__ edges) {
    long long i = ((long long)blockIdx.x * blockDim.x + threadIdx.x) * 2;
    if (i >= E) return;
    int s0, d0, s1 = -1, d1 = -1;
    if (g_is64) {
        const long long* ps = (const long long*)ei;
        const long long* pd = ps + E;
        if (i + 1 < E) {
            longlong2 vs = *(const longlong2*)(ps + i);
            longlong2 vd = *(const longlong2*)(pd + i);
            s0 = (int)vs.x; s1 = (int)vs.y; d0 = (int)vd.x; d1 = (int)vd.y;
        } else { s0 = (int)ps[i]; d0 = (int)pd[i]; }
    } else {
        const int* ps = (const int*)ei;
        const int* pd = ps + E;
        if (i + 1 < E) {
            int2 vs = *(const int2*)(ps + i);
            int2 vd = *(const int2*)(pd + i);
            s0 = vs.x; s1 = vs.y; d0 = vd.x; d1 = vd.y;
        } else { s0 = ps[i]; d0 = pd[i]; }
    }
    {
        unsigned pos = atomicAdd(&curs[d0], 1u);
        float nrm = dis[s0] * dis[d0];
        edges[pos] = make_int2(s0, __float_as_int(nrm));
    }
    if (s1 >= 0) {
        unsigned pos = atomicAdd(&curs[d1], 1u);
        float nrm = dis[s1] * dis[d1];
        edges[pos] = make_int2(s1, __float_as_int(nrm));
    }
}

// ---------------- standalone GEMM1: m1 = x @ W1^T (fp16 out) -------------
__global__ __launch_bounds__(256) void k_mm1(
    const float* __restrict__ hin, const uint4* __restrict__ frag,
    __half* __restrict__ out)
{
    extern __shared__ char smem[];
    constexpr int APL = 128 * KP * 2;
    const int AH = 0, AL = APL;
    constexpr int NTI = 8;                   // WN=64, n8-tiles per warp

    const uint32_t sb = smem_u32(smem);
    const int t = threadIdx.x;
    const int w = t >> 5, lane = t & 31;
    const int node0 = blockIdx.x * 128;

    #pragma unroll
    for (int idx = t; idx < 128 * 32; idx += 256) {
        int row = idx >> 5, kq = idx & 31;
        int node = node0 + row;
        float4 v = make_float4(0.f, 0.f, 0.f, 0.f);
        if (node < NN) v = __ldg((const float4*)(hin + (size_t)node * 128 + kq * 4));
        uint2 hi, lo;
        split4(v, hi, lo);
        int boff = (row * KP + kq * 4) * 2;
        *(uint2*)(smem + AH + boff) = hi;
        *(uint2*)(smem + AL + boff) = lo;
    }
    __syncthreads();

    const int wm = w >> 1, wn = w & 1;
    float acc[2][NTI][4];
    #pragma unroll
    for (int mi = 0; mi < 2; mi++)
        #pragma unroll
        for (int ni = 0; ni < NTI; ni++)
            #pragma unroll
            for (int j = 0; j < 4; j++) acc[mi][ni][j] = 0.f;

    const int tl = lane >> 3, r8 = lane & 7;
    const uint32_t arow = (uint32_t)((wm * 32 + (tl & 1) * 8 + r8) * KP + (tl >> 1) * 8) * 2;

    #pragma unroll
    for (int ks = 0; ks < 8; ks++) {
        const uint32_t kof = (uint32_t)(ks * 16) * 2;
        uint32_t ah[2][4], al[2][4];
        #pragma unroll
        for (int mi = 0; mi < 2; mi++) {
            uint32_t ad = sb + arow + (uint32_t)(mi * 16 * KP) * 2 + kof;
            ldsm_x4(ah[mi], ad + AH);
            ldsm_x4(al[mi], ad + AL);
        }
        #pragma unroll
        for (int ni = 0; ni < NTI; ni++) {
            uint4 f = __ldg(&frag[(size_t)((ks * 16 + wn * NTI + ni) * 32 + lane)]);
            uint32_t bh[2] = {f.x, f.y};
            uint32_t bl[2] = {f.z, f.w};
            #pragma unroll
            for (int mi = 0; mi < 2; mi++) {
                mma_bf16(acc[mi][ni], ah[mi], bh);
                mma_bf16(acc[mi][ni], ah[mi], bl);
                mma_bf16(acc[mi][ni], al[mi], bh);
            }
        }
    }

    const int g = lane >> 2, tg = lane & 3;
    #pragma unroll
    for (int mi = 0; mi < 2; mi++) {
        int rb = node0 + wm * 32 + mi * 16;
        #pragma unroll
        for (int ni = 0; ni < NTI; ni++) {
            int col = wn * 64 + ni * 8 + tg * 2;
            int n1 = rb + g, n2 = rb + g + 8;
            __half2 p01 = __floats2half2_rn(acc[mi][ni][0], acc[mi][ni][1]);
            __half2 p23 = __floats2half2_rn(acc[mi][ni][2], acc[mi][ni][3]);
            if (n1 < NN) *(__half2*)(out + (size_t)n1 * DH + col) = p01;
            if (n2 < NN) *(__half2*)(out + (size_t)n2 * DH + col) = p23;
        }
    }
}

// ---------------- fused aggregate + GEMM -------------------------------
// Phase 1: 8 warps x 16 nodes; half-warp split gather of m[src]; epilogue
//          relu(acc+b)+res -> (optional global h) + bf16 hi/lo smem A-planes.
// Phase 2: 128xNT GEMM from smem A (same mma loop as k_mm).
template <int NT, bool HEAD, bool WRITE_H>
__global__ __launch_bounds__(256) void k_fused(
    const int2* __restrict__ edges, const unsigned* __restrict__ off,
    const float* __restrict__ dis, const __half* __restrict__ m,
    const float* __restrict__ biasA, const float* __restrict__ res,
    float* __restrict__ hout,
    const uint4* __restrict__ frag, const float* __restrict__ biasG,
    void* __restrict__ outv)
{
    extern __shared__ char smem[];
    constexpr int APL = 128 * KP * 2;
    const int AH = 0, AL = APL;
    constexpr int WN = NT / 2;
    constexpr int NTI = WN / 8;
    constexpr int NT8 = NT / 8;

    const uint32_t sb = smem_u32(smem);
    const int t = threadIdx.x;
    const int w = t >> 5, lane = t & 31;
    const int hf = lane >> 4, l16 = lane & 15;
    const int co = l16 * 8;
    const int node0 = blockIdx.x * 128;

    // ---- phase 1: aggregate 16 nodes per warp ----
    for (int i = 0; i < 16; i++) {
        int row = w * 16 + i;
        int node = node0 + row;
        uint32_t aoff = (uint32_t)(row * KP + co) * 2;
        if (node >= NN) {
            if (hf == 0) {
                *(uint4*)(smem + AH + aoff) = make_uint4(0, 0, 0, 0);
                *(uint4*)(smem + AL + aoff) = make_uint4(0, 0, 0, 0);
            }
            continue;
        }
        unsigned e0 = off[node];
        unsigned cnt = off[node + 1] - e0;
        unsigned mA = (cnt + 1) >> 1;
        unsigned myCnt = hf ? (cnt - mA) : mA;
        const int2* ep = edges + e0 + (hf ? mA : 0);

        float d = dis[node];
        float sd = hf ? 0.f : (d * d);

        float a0[8], a1[8];
        #pragma unroll
        for (int j = 0; j < 8; j++) { a0[j] = 0.f; a1[j] = 0.f; }
        {
            uint4 mw = *(const uint4*)(m + (size_t)node * DH + co);
            acc8(a0, mw, sd);
        }
        unsigned k = 0;
        for (; k + 2 <= myCnt; k += 2) {
            int2 ea = __ldg(&ep[k]);
            int2 eb = __ldg(&ep[k + 1]);
            uint4 va = *(const uint4*)(m + (size_t)ea.x * DH + co);
            uint4 vb = *(const uint4*)(m + (size_t)eb.x * DH + co);
            acc8(a0, va, __int_as_float(ea.y));
            acc8(a1, vb, __int_as_float(eb.y));
        }
        if (k < myCnt) {
            int2 ea = __ldg(&ep[k]);
            uint4 va = *(const uint4*)(m + (size_t)ea.x * DH + co);
            acc8(a0, va, __int_as_float(ea.y));
        }
        float r[8];
        #pragma unroll
        for (int j = 0; j < 8; j++) r[j] = a0[j] + a1[j];
        #pragma unroll
        for (int j = 0; j < 8; j++) r[j] += __shfl_xor_sync(~0u, r[j], 16);

        if (hf == 0) {
            float4 b0 = __ldg(&((const float4*)biasA)[l16 * 2]);
            float4 b1 = __ldg(&((const float4*)biasA)[l16 * 2 + 1]);
            const float4* rr = (const float4*)(res + (size_t)node * DH + co);
            float4 r0 = rr[0], r1 = rr[1];
            float4 o0, o1;
            o0.x = fmaxf(r[0] + b0.x, 0.f) + r0.x;
            o0.y = fmaxf(r[1] + b0.y, 0.f) + r0.y;
            o0.z = fmaxf(r[2] + b0.z, 0.f) + r0.z;
            o0.w = fmaxf(r[3] + b0.w, 0.f) + r0.w;
            o1.x = fmaxf(r[4] + b1.x, 0.f) + r1.x;
            o1.y = fmaxf(r[5] + b1.y, 0.f) + r1.y;
            o1.z = fmaxf(r[6] + b1.z, 0.f) + r1.z;
            o1.w = fmaxf(r[7] + b1.w, 0.f) + r1.w;
            if (WRITE_H) {
                float4* po = (float4*)(hout + (size_t)node * DH + co);
                po[0] = o0;
                po[1] = o1;
            }
            uint2 h0, l0, h1, l1;
            split4(o0, h0, l0);
            split4(o1, h1, l1);
            *(uint4*)(smem + AH + aoff) = make_uint4(h0.x, h0.y, h1.x, h1.y);
            *(uint4*)(smem + AL + aoff) = make_uint4(l0.x, l0.y, l1.x, l1.y);
        }
    }
    __syncthreads();

    // ---- phase 2: GEMM from smem A ----
    const int wm = w >> 1, wn = w & 1;
    float acc[2][NTI][4];
    #pragma unroll
    for (int mi = 0; mi < 2; mi++)
        #pragma unroll
        for (int ni = 0; ni < NTI; ni++)
            #pragma unroll
            for (int j = 0; j < 4; j++) acc[mi][ni][j] = 0.f;

    const int tl = lane >> 3, r8 = lane & 7;
    const uint32_t arow = (uint32_t)((wm * 32 + (tl & 1) * 8 + r8) * KP + (tl >> 1) * 8) * 2;

    #pragma unroll
    for (int ks = 0; ks < 8; ks++) {
        const uint32_t kof = (uint32_t)(ks * 16) * 2;
        uint32_t ah[2][4], al[2][4];
        #pragma unroll
        for (int mi = 0; mi < 2; mi++) {
            uint32_t ad = sb + arow + (uint32_t)(mi * 16 * KP) * 2 + kof;
            ldsm_x4(ah[mi], ad + AH);
            ldsm_x4(al[mi], ad + AL);
        }
        #pragma unroll
        for (int ni = 0; ni < NTI; ni++) {
            uint4 f = __ldg(&frag[(size_t)((ks * NT8 + wn * NTI + ni) * 32 + lane)]);
            uint32_t bh[2] = {f.x, f.y};
            uint32_t bl[2] = {f.z, f.w};
            #pragma unroll
            for (int mi = 0; mi < 2; mi++) {
                mma_bf16(acc[mi][ni], ah[mi], bh);
                mma_bf16(acc[mi][ni], ah[mi], bl);
                mma_bf16(acc[mi][ni], al[mi], bh);
            }
        }
    }

    const int g = lane >> 2, tg = lane & 3;
    #pragma unroll
    for (int mi = 0; mi < 2; mi++) {
        int rb = node0 + wm * 32 + mi * 16;
        #pragma unroll
        for (int ni = 0; ni < NTI; ni++) {
            int col = wn * WN + ni * 8 + tg * 2;
            int n1 = rb + g, n2 = rb + g + 8;
            if (HEAD) {
                float2 c01 = make_float2(acc[mi][ni][0], acc[mi][ni][1]);
                float2 c23 = make_float2(acc[mi][ni][2], acc[mi][ni][3]);
                float2 bb = *(const float2*)(biasG + col);
                c01.x += bb.x; c01.y += bb.y;
                c23.x += bb.x; c23.y += bb.y;
                float* out = (float*)outv;
                if (n1 < NN) *(float2*)(out + (size_t)n1 * NT + col) = c01;
                if (n2 < NN) *(float2*)(out + (size_t)n2 * NT + col) = c23;
            } else {
                __half* out = (__half*)outv;
                __half2 p01 = __floats2half2_rn(acc[mi][ni][0], acc[mi][ni][1]);
                __half2 p23 = __floats2half2_rn(acc[mi][ni][2], acc[mi][ni][3]);
                if (n1 < NN) *(__half2*)(out + (size_t)n1 * NT + col) = p01;
                if (n2 < NN) *(__half2*)(out + (size_t)n2 * NT + col) = p23;
            }
        }
    }
}

// ---------------- launch ----------------
extern "C" void kernel_launch(void* const* d_in, const int* in_sizes, int n_in,
                              void* d_out, int out_size) {
    const float* x  = (const float*)d_in[0];
    const void*  ei = d_in[1];
    const float* W1 = (const float*)d_in[2];
    const float* b1 = (const float*)d_in[3];
    const float* W2 = (const float*)d_in[4];
    const float* b2 = (const float*)d_in[5];
    const float* Wl = (const float*)d_in[6];
    const float* bl = (const float*)d_in[7];
    long long E = (long long)in_sizes[1] / 2;

    __half *m1, *m2;
    float *h, *dis;
    unsigned *deg, *part, *bsum, *off, *curs;
    int2* edges;
    uint4 *wf1, *wf2, *wfl;
    cudaGetSymbolAddress((void**)&m1,    g_m1);
    cudaGetSymbolAddress((void**)&m2,    g_m2);
    cudaGetSymbolAddress((void**)&h,     g_h);
    cudaGetSymbolAddress((void**)&dis,   g_dis);
    cudaGetSymbolAddress((void**)&deg,   g_deg);
    cudaGetSymbolAddress((void**)&part,  g_part);
    cudaGetSymbolAddress((void**)&bsum,  g_bsum);
    cudaGetSymbolAddress((void**)&off,   g_off);
    cudaGetSymbolAddress((void**)&curs,  g_curs);
    cudaGetSymbolAddress((void**)&edges, g_edge);
    cudaGetSymbolAddress((void**)&wf1,   g_wf1);
    cudaGetSymbolAddress((void**)&wf2,   g_wf2);
    cudaGetSymbolAddress((void**)&wfl,   g_wfl);

    const int SMEM_MM = 2 * (128 * KP * 2);      // 69632 (A planes only)
    cudaFuncSetAttribute(k_mm1, cudaFuncAttributeMaxDynamicSharedMemorySize, SMEM_MM);
    cudaFuncSetAttribute(k_fused<DH, false, true>,
                         cudaFuncAttributeMaxDynamicSharedMemorySize, SMEM_MM);
    cudaFuncSetAttribute(k_fused<CC, true, false>,
                         cudaFuncAttributeMaxDynamicSharedMemorySize, SMEM_MM);

    cudaStream_t s2;
    cudaStreamCreateWithFlags(&s2, cudaStreamNonBlocking);
    cudaEvent_t evF, evM1;
    cudaEventCreateWithFlags(&evF,  cudaEventDisableTiming);
    cudaEventCreateWithFlags(&evM1, cudaEventDisableTiming);

    const unsigned dblocks = (unsigned)(((E + 1) / 2 + 255) / 256);
    const int MB = (NN + 127) / 128;            // 782

    // fork: GEMM1 + wfrag overlap CSR build
    cudaEventRecord(evF, 0);
    cudaStreamWaitEvent(s2, evF, 0);

    k_wfrag<<<(10240 + 255) / 256, 256, 0, s2>>>(W1, W2, Wl, wf1, wf2, wfl);
    k_mm1<<<MB, 256, SMEM_MM, s2>>>(x, wf1, m1);
    cudaEventRecord(evM1, s2);

    k_initdet<<<(NN + 255) / 256, 256>>>((const int*)ei, deg);
    k_deg<<<dblocks, 256>>>(ei, E, deg);
    k_scan1<<<NB_SCAN, 1024>>>(deg, part, bsum);
    k_scan2<<<1, 128>>>(bsum);
    k_scan3<<<(NN + 255) / 256, 256>>>(deg, part, bsum, off, curs, dis, E);
    k_place<<<dblocks, 256>>>(ei, E, dis, curs, edges);

    cudaStreamWaitEvent(0, evM1, 0);

    // fused layer 1+2: aggr(m1) -> h (global) -> GEMM(W2) -> m2
    k_fused<DH, false, true><<<MB, 256, SMEM_MM>>>(
        edges, off, dis, m1, b1, x, h, wf2, nullptr, m2);

    // fused layer 2+head: aggr(m2, res=h) -> smem only -> GEMM(Wl) -> out
    k_fused<CC, true, false><<<MB, 256, SMEM_MM>>>(
        edges, off, dis, m2, b2, h, nullptr, wfl, bl, d_out);
}

// round 15
// speedup vs baseline: 1.1799x; 1.1799x over previous
#include <cuda_runtime.h>
#include <cuda_bf16.h>
#include <cuda_fp16.h>
#include <cstdint>

#define NN 100000
#define EE 1600000
#define DH 128
#define CC 64
#define NB_SCAN 98          // ceil(NN/1024)
#define KP 136              // bf16 row stride (272B) -> conflict-free ldmatrix
#define CHUNK 50048         // node split for pipelining (391 gemm blocks)

// ---------------- device scratch (static, no allocs) ----------------
__device__ __half   g_m1[(size_t)NN * DH];   // m buffers (fp16, ping-pong)
__device__ __half   g_m2[(size_t)NN * DH];
__device__ float    g_h[(size_t)NN * DH];    // layer activations
__device__ float    g_dis[NN];               // deg^{-1/2}
__device__ unsigned g_deg[NN];               // 1 + in-degree
__device__ unsigned g_part[NN];              // scan partials
__device__ unsigned g_bsum[NB_SCAN];
__device__ unsigned g_off[NN + 1];           // CSR offsets
__device__ unsigned g_curs[NN];              // placement cursors
__device__ int2     g_edge[EE + 2];          // {src, bitcast(nrm)}
__device__ uint4    g_wf1[8 * 16 * 32];      // W mma B-fragments (hi,lo)
__device__ uint4    g_wf2[8 * 16 * 32];
__device__ uint4    g_wfl[8 * 8 * 32];
__device__ int      g_is64;

// ---------------- PTX helpers (plain sm_103-safe) ----------------
__device__ __forceinline__ uint32_t smem_u32(const void* p) {
    uint32_t a;
    asm("{ .reg .u64 t; cvta.to.shared.u64 t, %1; cvt.u32.u64 %0, t; }"
        : "=r"(a) : "l"(p));
    return a;
}
__device__ __forceinline__ void ldsm_x4(uint32_t* r, uint32_t addr) {
    asm volatile("ldmatrix.sync.aligned.m8n8.x4.shared.b16 {%0,%1,%2,%3}, [%4];"
                 : "=r"(r[0]), "=r"(r[1]), "=r"(r[2]), "=r"(r[3]) : "r"(addr));
}
__device__ __forceinline__ void mma_bf16(float* c, const uint32_t* a,
                                         const uint32_t* b) {
    asm volatile(
        "mma.sync.aligned.m16n8k16.row.col.f32.bf16.bf16.f32 "
        "{%0,%1,%2,%3}, {%4,%5,%6,%7}, {%8,%9}, {%0,%1,%2,%3};"
        : "+f"(c[0]), "+f"(c[1]), "+f"(c[2]), "+f"(c[3])
        : "r"(a[0]), "r"(a[1]), "r"(a[2]), "r"(a[3]), "r"(b[0]), "r"(b[1]));
}

// pack float4 -> hi bf16x2 pair + lo bf16x2 pair
__device__ __forceinline__ void split4(float4 v, uint2& hi, uint2& lo) {
    __nv_bfloat162 h01 = __floats2bfloat162_rn(v.x, v.y);
    __nv_bfloat162 h23 = __floats2bfloat162_rn(v.z, v.w);
    float lx = v.x - __bfloat162float(h01.x);
    float ly = v.y - __bfloat162float(h01.y);
    float lz = v.z - __bfloat162float(h23.x);
    float lw = v.w - __bfloat162float(h23.y);
    __nv_bfloat162 l01 = __floats2bfloat162_rn(lx, ly);
    __nv_bfloat162 l23 = __floats2bfloat162_rn(lz, lw);
    hi.x = *(uint32_t*)&h01; hi.y = *(uint32_t*)&h23;
    lo.x = *(uint32_t*)&l01; lo.y = *(uint32_t*)&l23;
}

// accumulate 8 fp16 cols (uint4) scaled by n into acc[8]
__device__ __forceinline__ void acc8(float* acc, uint4 v, float n) {
    float2 p0 = __half22float2(*(__half2*)&v.x);
    float2 p1 = __half22float2(*(__half2*)&v.y);
    float2 p2 = __half22float2(*(__half2*)&v.z);
    float2 p3 = __half22float2(*(__half2*)&v.w);
    acc[0] = fmaf(p0.x, n, acc[0]); acc[1] = fmaf(p0.y, n, acc[1]);
    acc[2] = fmaf(p1.x, n, acc[2]); acc[3] = fmaf(p1.y, n, acc[3]);
    acc[4] = fmaf(p2.x, n, acc[4]); acc[5] = fmaf(p2.y, n, acc[5]);
    acc[6] = fmaf(p3.x, n, acc[6]); acc[7] = fmaf(p3.y, n, acc[7]);
}

// ---------------- setup: deg init + dtype detect + W fragments ----------
__global__ void k_pre(const int* __restrict__ w, unsigned* __restrict__ deg,
                      const float* __restrict__ W1, const float* __restrict__ W2,
                      const float* __restrict__ Wl,
                      uint4* __restrict__ f1, uint4* __restrict__ f2,
                      uint4* __restrict__ fl) {
    int i = blockIdx.x * blockDim.x + threadIdx.x;
    if (i < NN) deg[i] = 1u;                 // self-loop
    if (blockIdx.x == 0) {
        bool nz = (w[2 * threadIdx.x + 1] != 0);
        int any = __syncthreads_or((int)nz);
        if (threadIdx.x == 0) g_is64 = !any; // int64 vals < 2^31 -> odd words 0
    }
    // W mma B-fragments
    if (i < 10240) {
        const float* W; uint4* F; int NT8, j;
        if (i < 4096)      { W = W1; F = f1; NT8 = 16; j = i; }
        else if (i < 8192) { W = W2; F = f2; NT8 = 16; j = i - 4096; }
        else               { W = Wl; F = fl; NT8 = 8;  j = i - 8192; }
        int lane = j & 31, t = j >> 5;
        int ni = t % NT8, ks = t / NT8;
        int n = ni * 8 + (lane >> 2);
        int k = ks * 16 + (lane & 3) * 2;
        const float* r = W + (size_t)n * 128;
        float w0 = r[k], w1 = r[k + 1], w2 = r[k + 8], w3 = r[k + 9];
        uint2 hi, lo;
        split4(make_float4(w0, w1, w2, w3), hi, lo);
        F[j] = make_uint4(hi.x, hi.y, lo.x, lo.y);
    }
}

__global__ void k_deg(const void* __restrict__ ei, long long E,
                      unsigned* __restrict__ deg) {
    long long i = ((long long)blockIdx.x * blockDim.x + threadIdx.x) * 2;
    if (i >= E) return;
    int d0, d1 = -1;
    if (g_is64) {
        const long long* p = (const long long*)ei + E;
        d0 = (int)__ldcs(&p[i]);
        if (i + 1 < E) d1 = (int)__ldcs(&p[i + 1]);
    } else {
        const int* p = (const int*)ei + E;
        d0 = __ldcs(&p[i]);
        if (i + 1 < E) d1 = __ldcs(&p[i + 1]);
    }
    atomicAdd(&deg[d0], 1u);
    if (d1 >= 0) atomicAdd(&deg[d1], 1u);
}

// ---------------- CSR build ----------------
__global__ __launch_bounds__(1024) void k_scan1(const unsigned* __restrict__ deg,
                                                unsigned* __restrict__ part,
                                                unsigned* __restrict__ bsum) {
    __shared__ unsigned ws[32];
    int t = threadIdx.x;
    int i = blockIdx.x * 1024 + t;
    unsigned x = (i < NN) ? (deg[i] - 1u) : 0u;
    #pragma unroll
    for (int o = 1; o < 32; o <<= 1) {
        unsigned y = __shfl_up_sync(~0u, x, o);
        if ((t & 31) >= o) x += y;
    }
    if ((t & 31) == 31) ws[t >> 5] = x;
    __syncthreads();
    if (t < 32) {
        unsigned w = ws[t];
        #pragma unroll
        for (int o = 1; o < 32; o <<= 1) {
            unsigned y = __shfl_up_sync(~0u, w, o);
            if (t >= o) w += y;
        }
        ws[t] = w;
    }
    __syncthreads();
    if (t >= 32) x += ws[(t >> 5) - 1];
    if (i < NN) part[i] = x;
    if (t == 1023) bsum[blockIdx.x] = x;
}

// scan3 with local exclusive scan of bsum (replaces scan2+scan3)
__global__ void k_scan3(const unsigned* __restrict__ deg,
                        const unsigned* __restrict__ part,
                        const unsigned* __restrict__ bsum,
                        unsigned* __restrict__ off, unsigned* __restrict__ curs,
                        float* __restrict__ dis, long long E) {
    __shared__ unsigned spref[NB_SCAN];
    int t = threadIdx.x;
    if (t == 0) {
        unsigned run = 0;
        for (int k = 0; k < NB_SCAN; k++) { unsigned v = bsum[k]; spref[k] = run; run += v; }
    }
    __syncthreads();
    int i = blockIdx.x * blockDim.x + t;
    if (i < NN) {
        unsigned dg = deg[i];
        unsigned incl = part[i] + spref[i >> 10];
        unsigned excl = incl - (dg - 1u);
        off[i] = excl;
        curs[i] = excl;
        dis[i] = rsqrtf((float)dg);
    }
    if (i == 0) off[NN] = (unsigned)E;
}

__global__ void k_place(const void* __restrict__ ei, long long E,
                        const float* __restrict__ dis, unsigned* __restrict__ curs,
                        int2* __restrict__ edges) {
    long long i = ((long long)blockIdx.x * blockDim.x + threadIdx.x) * 2;
    if (i >= E) return;
    int s0, d0, s1 = -1, d1 = -1;
    if (g_is64) {
        const long long* ps = (const long long*)ei;
        const long long* pd = ps + E;
        s0 = (int)__ldcs(&ps[i]);
        d0 = (int)__ldcs(&pd[i]);
        if (i + 1 < E) { s1 = (int)__ldcs(&ps[i + 1]); d1 = (int)__ldcs(&pd[i + 1]); }
    } else {
        const int* ps = (const int*)ei;
        const int* pd = ps + E;
        s0 = __ldcs(&ps[i]);
        d0 = __ldcs(&pd[i]);
        if (i + 1 < E) { s1 = __ldcs(&ps[i + 1]); d1 = __ldcs(&pd[i + 1]); }
    }
    {
        unsigned pos = atomicAdd(&curs[d0], 1u);
        float nrm = dis[s0] * dis[d0];
        edges[pos] = make_int2(s0, __float_as_int(nrm));
    }
    if (s1 >= 0) {
        unsigned pos = atomicAdd(&curs[d1], 1u);
        float nrm = dis[s1] * dis[d1];
        edges[pos] = make_int2(s1, __float_as_int(nrm));
    }
}

// ---------------- bf16 split-3 HMMA GEMM: out = hin @ W^T ----------------
template <int NT, bool HEAD>
__global__ __launch_bounds__(256) void k_mm(
    const float* __restrict__ hin, const uint4* __restrict__ frag,
    const float* __restrict__ bias, void* __restrict__ outv, int base)
{
    extern __shared__ char smem[];
    constexpr int APL = 128 * KP * 2;            // one A plane (bytes)
    const int AH = 0, AL = APL;
    constexpr int WN = NT / 2;
    constexpr int NTI = WN / 8;
    constexpr int NT8 = NT / 8;

    const uint32_t sb = smem_u32(smem);
    const int t = threadIdx.x;
    const int w = t >> 5, lane = t & 31;
    const int node0 = base + blockIdx.x * 128;

    #pragma unroll
    for (int idx = t; idx < 128 * 32; idx += 256) {
        int row = idx >> 5, kq = idx & 31;
        int node = node0 + row;
        float4 v = make_float4(0.f, 0.f, 0.f, 0.f);
        if (node < NN) v = __ldg((const float4*)(hin + (size_t)node * 128 + kq * 4));
        uint2 hi, lo;
        split4(v, hi, lo);
        int boff = (row * KP + kq * 4) * 2;
        *(uint2*)(smem + AH + boff) = hi;
        *(uint2*)(smem + AL + boff) = lo;
    }
    __syncthreads();

    const int wm = w >> 1, wn = w & 1;
    float acc[2][NTI][4];
    #pragma unroll
    for (int mi = 0; mi < 2; mi++)
        #pragma unroll
        for (int ni = 0; ni < NTI; ni++)
            #pragma unroll
            for (int j = 0; j < 4; j++) acc[mi][ni][j] = 0.f;

    const int tl = lane >> 3, r8 = lane & 7;
    const uint32_t arow = (uint32_t)((wm * 32 + (tl & 1) * 8 + r8) * KP + (tl >> 1) * 8) * 2;

    #pragma unroll
    for (int ks = 0; ks < 8; ks++) {
        const uint32_t kof = (uint32_t)(ks * 16) * 2;
        uint32_t ah[2][4], al[2][4];
        #pragma unroll
        for (int mi = 0; mi < 2; mi++) {
            uint32_t ad = sb + arow + (uint32_t)(mi * 16 * KP) * 2 + kof;
            ldsm_x4(ah[mi], ad + AH);
            ldsm_x4(al[mi], ad + AL);
        }
        #pragma unroll
        for (int ni = 0; ni < NTI; ni++) {
            uint4 f = __ldg(&frag[(size_t)((ks * NT8 + wn * NTI + ni) * 32 + lane)]);
            uint32_t bh[2] = {f.x, f.y};
            uint32_t bl[2] = {f.z, f.w};
            #pragma unroll
            for (int mi = 0; mi < 2; mi++) {
                mma_bf16(acc[mi][ni], ah[mi], bh);
                mma_bf16(acc[mi][ni], ah[mi], bl);
                mma_bf16(acc[mi][ni], al[mi], bh);
            }
        }
    }

    const int g = lane >> 2, tg = lane & 3;
    #pragma unroll
    for (int mi = 0; mi < 2; mi++) {
        int rb = node0 + wm * 32 + mi * 16;
        #pragma unroll
        for (int ni = 0; ni < NTI; ni++) {
            int col = wn * WN + ni * 8 + tg * 2;
            int n1 = rb + g, n2 = rb + g + 8;
            if (HEAD) {
                float2 c01 = make_float2(acc[mi][ni][0], acc[mi][ni][1]);
                float2 c23 = make_float2(acc[mi][ni][2], acc[mi][ni][3]);
                float2 bb = *(const float2*)(bias + col);
                c01.x += bb.x; c01.y += bb.y;
                c23.x += bb.x; c23.y += bb.y;
                float* out = (float*)outv;
                if (n1 < NN) *(float2*)(out + (size_t)n1 * NT + col) = c01;
                if (n2 < NN) *(float2*)(out + (size_t)n2 * NT + col) = c23;
            } else {
                __half* out = (__half*)outv;
                __half2 p01 = __floats2half2_rn(acc[mi][ni][0], acc[mi][ni][1]);
                __half2 p23 = __floats2half2_rn(acc[mi][ni][2], acc[mi][ni][3]);
                if (n1 < NN) *(__half2*)(out + (size_t)n1 * DH + col) = p01;
                if (n2 < NN) *(__half2*)(out + (size_t)n2 * DH + col) = p23;
            }
        }
    }
}

// ---------------- fused aggregate + epilogue (fp16 m, half-warp split) ----
// RSTREAM: residual is read-once (layer 1, res=x) -> evict-first loads.
template <bool RSTREAM>
__global__ __launch_bounds__(128) void k_aggr(
    const int2* __restrict__ edges, const unsigned* __restrict__ off,
    const float* __restrict__ dis, const __half* __restrict__ m,
    const float* __restrict__ bias, const float* __restrict__ res,
    float* __restrict__ ho, int base)
{
    int node = base + blockIdx.x * 4 + (threadIdx.x >> 5);
    if (node >= NN) return;
    const int lane = threadIdx.x & 31;
    const int hf = lane >> 4;                 // half-warp id
    const int l16 = lane & 15;
    const int co = l16 * 8;                   // column offset (8 halfs = 16B)

    unsigned e0 = off[node];
    unsigned cnt = off[node + 1] - e0;
    unsigned mA = (cnt + 1) >> 1;             // edges in half 0
    unsigned myCnt = hf ? (cnt - mA) : mA;
    const int2* ep = edges + e0 + (hf ? mA : 0);

    float d = dis[node];
    float sd = hf ? 0.f : (d * d);            // self term only on half 0

    float a0[8], a1[8];
    #pragma unroll
    for (int j = 0; j < 8; j++) { a0[j] = 0.f; a1[j] = 0.f; }

    {
        uint4 mw = *(const uint4*)(m + (size_t)node * DH + co);
        acc8(a0, mw, sd);
    }

    unsigned k = 0;
    for (; k + 2 <= myCnt; k += 2) {
        int2 ea = __ldcs(&ep[k]);
        int2 eb = __ldcs(&ep[k + 1]);
        uint4 va = *(const uint4*)(m + (size_t)ea.x * DH + co);
        uint4 vb = *(const uint4*)(m + (size_t)eb.x * DH + co);
        acc8(a0, va, __int_as_float(ea.y));
        acc8(a1, vb, __int_as_float(eb.y));
    }
    if (k < myCnt) {
        int2 ea = __ldcs(&ep[k]);
        uint4 va = *(const uint4*)(m + (size_t)ea.x * DH + co);
        acc8(a0, va, __int_as_float(ea.y));
    }

    float r[8];
    #pragma unroll
    for (int j = 0; j < 8; j++) r[j] = a0[j] + a1[j];
    #pragma unroll
    for (int j = 0; j < 8; j++) r[j] += __shfl_xor_sync(~0u, r[j], 16);

    if (hf == 0) {
        float4 b0 = __ldg(&((const float4*)bias)[l16 * 2]);
        float4 b1 = __ldg(&((const float4*)bias)[l16 * 2 + 1]);
        const float4* rr = (const float4*)(res + (size_t)node * DH + co);
        float4 r0, r1;
        if (RSTREAM) { r0 = __ldcs(&rr[0]); r1 = __ldcs(&rr[1]); }
        else         { r0 = rr[0];          r1 = rr[1]; }
        float4 o0, o1;
        o0.x = fmaxf(r[0] + b0.x, 0.f) + r0.x;
        o0.y = fmaxf(r[1] + b0.y, 0.f) + r0.y;
        o0.z = fmaxf(r[2] + b0.z, 0.f) + r0.z;
        o0.w = fmaxf(r[3] + b0.w, 0.f) + r0.w;
        o1.x = fmaxf(r[4] + b1.x, 0.f) + r1.x;
        o1.y = fmaxf(r[5] + b1.y, 0.f) + r1.y;
        o1.z = fmaxf(r[6] + b1.z, 0.f) + r1.z;
        o1.w = fmaxf(r[7] + b1.w, 0.f) + r1.w;
        float4* po = (float4*)(ho + (size_t)node * DH + co);
        po[0] = o0;
        po[1] = o1;
    }
}

// ---------------- launch (forked-graph DAG, chunk-pipelined tail) --------
extern "C" void kernel_launch(void* const* d_in, const int* in_sizes, int n_in,
                              void* d_out, int out_size) {
    const float* x  = (const float*)d_in[0];
    const void*  ei = d_in[1];
    const float* W1 = (const float*)d_in[2];
    const float* b1 = (const float*)d_in[3];
    const float* W2 = (const float*)d_in[4];
    const float* b2 = (const float*)d_in[5];
    const float* Wl = (const float*)d_in[6];
    const float* bl = (const float*)d_in[7];
    long long E = (long long)in_sizes[1] / 2;

    __half *m1, *m2;
    float *h, *dis;
    unsigned *deg, *part, *bsum, *off, *curs;
    int2* edges;
    uint4 *wf1, *wf2, *wfl;
    cudaGetSymbolAddress((void**)&m1,    g_m1);
    cudaGetSymbolAddress((void**)&m2,    g_m2);
    cudaGetSymbolAddress((void**)&h,     g_h);
    cudaGetSymbolAddress((void**)&dis,   g_dis);
    cudaGetSymbolAddress((void**)&deg,   g_deg);
    cudaGetSymbolAddress((void**)&part,  g_part);
    cudaGetSymbolAddress((void**)&bsum,  g_bsum);
    cudaGetSymbolAddress((void**)&off,   g_off);
    cudaGetSymbolAddress((void**)&curs,  g_curs);
    cudaGetSymbolAddress((void**)&edges, g_edge);
    cudaGetSymbolAddress((void**)&wf1,   g_wf1);
    cudaGetSymbolAddress((void**)&wf2,   g_wf2);
    cudaGetSymbolAddress((void**)&wfl,   g_wfl);

    const int SMEM_MM = 2 * (128 * KP * 2);      // 69632 (A planes only)
    cudaFuncSetAttribute(k_mm<DH, false>, cudaFuncAttributeMaxDynamicSharedMemorySize, SMEM_MM);
    cudaFuncSetAttribute(k_mm<CC, true>,  cudaFuncAttributeMaxDynamicSharedMemorySize, SMEM_MM);

    cudaStream_t s2;
    cudaStreamCreateWithFlags(&s2, cudaStreamNonBlocking);
    cudaEvent_t evP, evM1, evH0, evH1, evM2a, evM2b, evG0, evG1, evD;
    cudaEventCreateWithFlags(&evP,   cudaEventDisableTiming);
    cudaEventCreateWithFlags(&evM1,  cudaEventDisableTiming);
    cudaEventCreateWithFlags(&evH0,  cudaEventDisableTiming);
    cudaEventCreateWithFlags(&evH1,  cudaEventDisableTiming);
    cudaEventCreateWithFlags(&evM2a, cudaEventDisableTiming);
    cudaEventCreateWithFlags(&evM2b, cudaEventDisableTiming);
    cudaEventCreateWithFlags(&evG0,  cudaEventDisableTiming);
    cudaEventCreateWithFlags(&evG1,  cudaEventDisableTiming);
    cudaEventCreateWithFlags(&evD,   cudaEventDisableTiming);

    const unsigned dblocks = (unsigned)(((E + 1) / 2 + 255) / 256);
    const int MB = 391;                         // gemm blocks per chunk
    const int AB0 = CHUNK / 4;                  // 128-thd aggr blocks (4 nodes)
    const int AB1 = (NN - CHUNK + 3) / 4;

    // prologue shared by both branches (deg init + detect + W fragments)
    k_pre<<<(NN + 255) / 256, 256>>>((const int*)ei, deg, W1, W2, Wl, wf1, wf2, wfl);
    cudaEventRecord(evP, 0);
    cudaStreamWaitEvent(s2, evP, 0);

    // ---- branch B (s2): GEMM1 ----
    k_mm<DH, false><<<2 * MB, 256, SMEM_MM, s2>>>(x, wf1, nullptr, m1, 0);
    cudaEventRecord(evM1, s2);

    // ---- branch A (stream 0): CSR build ----
    k_deg<<<dblocks, 256>>>(ei, E, deg);
    k_scan1<<<NB_SCAN, 1024>>>(deg, part, bsum);
    k_scan3<<<(NN + 255) / 256, 256>>>(deg, part, bsum, off, curs, dis, E);
    k_place<<<dblocks, 256>>>(ei, E, dis, curs, edges);

    // ---- join for aggr1, pipeline layer boundaries ----
    cudaStreamWaitEvent(0, evM1, 0);
    k_aggr<true><<<AB0, 128>>>(edges, off, dis, m1, b1, x, h, 0);
    cudaEventRecord(evH0, 0);
    k_aggr<true><<<AB1, 128>>>(edges, off, dis, m1, b1, x, h, CHUNK);
    cudaEventRecord(evH1, 0);

    cudaStreamWaitEvent(s2, evH0, 0);
    k_mm<DH, false><<<MB, 256, SMEM_MM, s2>>>(h, wf2, nullptr, m2, 0);
    cudaEventRecord(evM2a, s2);
    cudaStreamWaitEvent(s2, evH1, 0);
    k_mm<DH, false><<<MB, 256, SMEM_MM, s2>>>(h, wf2, nullptr, m2, CHUNK);
    cudaEventRecord(evM2b, s2);

    cudaStreamWaitEvent(0, evM2a, 0);
    cudaStreamWaitEvent(0, evM2b, 0);
    k_aggr<false><<<AB0, 128>>>(edges, off, dis, m2, b2, h, h, 0);
    cudaEventRecord(evG0, 0);
    k_aggr<false><<<AB1, 128>>>(edges, off, dis, m2, b2, h, h, CHUNK);
    cudaEventRecord(evG1, 0);

    cudaStreamWaitEvent(s2, evG0, 0);
    k_mm<CC, true><<<MB, 256, SMEM_MM, s2>>>(h, wfl, bl, d_out, 0);
    cudaStreamWaitEvent(s2, evG1, 0);
    k_mm<CC, true><<<MB, 256, SMEM_MM, s2>>>(h, wfl, bl, d_out, CHUNK);
    cudaEventRecord(evD, s2);

    // join back into origin stream (required for capture)
    cudaStreamWaitEvent(0, evD, 0);
}

// round 16
// speedup vs baseline: 1.2258x; 1.0389x over previous
#include <cuda_runtime.h>
#include <cuda_bf16.h>
#include <cuda_fp16.h>
#include <cstdint>

#define NN 100000
#define EE 1600000
#define DH 128
#define CC 64
#define NB_SCAN 98          // ceil(NN/1024)
#define KP 136              // bf16 row stride (272B) -> conflict-free ldmatrix
#define CHUNK 50048         // node split for pipelining (391 gemm blocks)

// ---------------- device scratch (static, no allocs) ----------------
__device__ __half   g_m1[(size_t)NN * DH];   // m buffers (fp16, ping-pong)
__device__ __half   g_m2[(size_t)NN * DH];
__device__ __half   g_h[(size_t)NN * DH];    // layer activations (fp16)
__device__ float    g_dis[NN];               // deg^{-1/2}
__device__ unsigned g_deg[NN];               // 1 + in-degree
__device__ unsigned g_part[NN];              // scan partials
__device__ unsigned g_bsum[NB_SCAN];
__device__ unsigned g_off[NN + 1];           // CSR offsets
__device__ unsigned g_curs[NN];              // placement cursors
__device__ int2     g_edge[EE + 2];          // {src, bitcast(nrm)}
__device__ uint4    g_wf1[8 * 16 * 32];      // W mma B-fragments (hi,lo)
__device__ uint4    g_wf2[8 * 16 * 32];
__device__ uint4    g_wfl[8 * 8 * 32];
__device__ int      g_is64;

// ---------------- PTX helpers (plain sm_103-safe) ----------------
__device__ __forceinline__ uint32_t smem_u32(const void* p) {
    uint32_t a;
    asm("{ .reg .u64 t; cvta.to.shared.u64 t, %1; cvt.u32.u64 %0, t; }"
        : "=r"(a) : "l"(p));
    return a;
}
__device__ __forceinline__ void ldsm_x4(uint32_t* r, uint32_t addr) {
    asm volatile("ldmatrix.sync.aligned.m8n8.x4.shared.b16 {%0,%1,%2,%3}, [%4];"
                 : "=r"(r[0]), "=r"(r[1]), "=r"(r[2]), "=r"(r[3]) : "r"(addr));
}
__device__ __forceinline__ void mma_bf16(float* c, const uint32_t* a,
                                         const uint32_t* b) {
    asm volatile(
        "mma.sync.aligned.m16n8k16.row.col.f32.bf16.bf16.f32 "
        "{%0,%1,%2,%3}, {%4,%5,%6,%7}, {%8,%9}, {%0,%1,%2,%3};"
        : "+f"(c[0]), "+f"(c[1]), "+f"(c[2]), "+f"(c[3])
        : "r"(a[0]), "r"(a[1]), "r"(a[2]), "r"(a[3]), "r"(b[0]), "r"(b[1]));
}

// pack float4 -> hi bf16x2 pair + lo bf16x2 pair
__device__ __forceinline__ void split4(float4 v, uint2& hi, uint2& lo) {
    __nv_bfloat162 h01 = __floats2bfloat162_rn(v.x, v.y);
    __nv_bfloat162 h23 = __floats2bfloat162_rn(v.z, v.w);
    float lx = v.x - __bfloat162float(h01.x);
    float ly = v.y - __bfloat162float(h01.y);
    float lz = v.z - __bfloat162float(h23.x);
    float lw = v.w - __bfloat162float(h23.y);
    __nv_bfloat162 l01 = __floats2bfloat162_rn(lx, ly);
    __nv_bfloat162 l23 = __floats2bfloat162_rn(lz, lw);
    hi.x = *(uint32_t*)&h01; hi.y = *(uint32_t*)&h23;
    lo.x = *(uint32_t*)&l01; lo.y = *(uint32_t*)&l23;
}

// accumulate 8 fp16 cols (uint4) scaled by n into acc[8]
__device__ __forceinline__ void acc8(float* acc, uint4 v, float n) {
    float2 p0 = __half22float2(*(__half2*)&v.x);
    float2 p1 = __half22float2(*(__half2*)&v.y);
    float2 p2 = __half22float2(*(__half2*)&v.z);
    float2 p3 = __half22float2(*(__half2*)&v.w);
    acc[0] = fmaf(p0.x, n, acc[0]); acc[1] = fmaf(p0.y, n, acc[1]);
    acc[2] = fmaf(p1.x, n, acc[2]); acc[3] = fmaf(p1.y, n, acc[3]);
    acc[4] = fmaf(p2.x, n, acc[4]); acc[5] = fmaf(p2.y, n, acc[5]);
    acc[6] = fmaf(p3.x, n, acc[6]); acc[7] = fmaf(p3.y, n, acc[7]);
}

// ---------------- setup: deg init + dtype detect + W fragments ----------
__global__ void k_pre(const int* __restrict__ w, unsigned* __restrict__ deg,
                      const float* __restrict__ W1, const float* __restrict__ W2,
                      const float* __restrict__ Wl,
                      uint4* __restrict__ f1, uint4* __restrict__ f2,
                      uint4* __restrict__ fl) {
    int i = blockIdx.x * blockDim.x + threadIdx.x;
    if (i < NN) deg[i] = 1u;                 // self-loop
    if (blockIdx.x == 0) {
        bool nz = (w[2 * threadIdx.x + 1] != 0);
        int any = __syncthreads_or((int)nz);
        if (threadIdx.x == 0) g_is64 = !any; // int64 vals < 2^31 -> odd words 0
    }
    if (i < 10240) {
        const float* W; uint4* F; int NT8, j;
        if (i < 4096)      { W = W1; F = f1; NT8 = 16; j = i; }
        else if (i < 8192) { W = W2; F = f2; NT8 = 16; j = i - 4096; }
        else               { W = Wl; F = fl; NT8 = 8;  j = i - 8192; }
        int lane = j & 31, t = j >> 5;
        int ni = t % NT8, ks = t / NT8;
        int n = ni * 8 + (lane >> 2);
        int k = ks * 16 + (lane & 3) * 2;
        const float* r = W + (size_t)n * 128;
        float w0 = r[k], w1 = r[k + 1], w2 = r[k + 8], w3 = r[k + 9];
        uint2 hi, lo;
        split4(make_float4(w0, w1, w2, w3), hi, lo);
        F[j] = make_uint4(hi.x, hi.y, lo.x, lo.y);
    }
}

__global__ void k_deg(const void* __restrict__ ei, long long E,
                      unsigned* __restrict__ deg) {
    long long i = ((long long)blockIdx.x * blockDim.x + threadIdx.x) * 2;
    if (i >= E) return;
    int d0, d1 = -1;
    if (g_is64) {
        const long long* p = (const long long*)ei + E;
        d0 = (int)__ldcs(&p[i]);
        if (i + 1 < E) d1 = (int)__ldcs(&p[i + 1]);
    } else {
        const int* p = (const int*)ei + E;
        d0 = __ldcs(&p[i]);
        if (i + 1 < E) d1 = __ldcs(&p[i + 1]);
    }
    atomicAdd(&deg[d0], 1u);
    if (d1 >= 0) atomicAdd(&deg[d1], 1u);
}

// ---------------- CSR build ----------------
__global__ __launch_bounds__(1024) void k_scan1(const unsigned* __restrict__ deg,
                                                unsigned* __restrict__ part,
                                                unsigned* __restrict__ bsum) {
    __shared__ unsigned ws[32];
    int t = threadIdx.x;
    int i = blockIdx.x * 1024 + t;
    unsigned x = (i < NN) ? (deg[i] - 1u) : 0u;
    #pragma unroll
    for (int o = 1; o < 32; o <<= 1) {
        unsigned y = __shfl_up_sync(~0u, x, o);
        if ((t & 31) >= o) x += y;
    }
    if ((t & 31) == 31) ws[t >> 5] = x;
    __syncthreads();
    if (t < 32) {
        unsigned w = ws[t];
        #pragma unroll
        for (int o = 1; o < 32; o <<= 1) {
            unsigned y = __shfl_up_sync(~0u, w, o);
            if (t >= o) w += y;
        }
        ws[t] = w;
    }
    __syncthreads();
    if (t >= 32) x += ws[(t >> 5) - 1];
    if (i < NN) part[i] = x;
    if (t == 1023) bsum[blockIdx.x] = x;
}

// scan3 with local exclusive scan of bsum (replaces scan2+scan3)
__global__ void k_scan3(const unsigned* __restrict__ deg,
                        const unsigned* __restrict__ part,
                        const unsigned* __restrict__ bsum,
                        unsigned* __restrict__ off, unsigned* __restrict__ curs,
                        float* __restrict__ dis, long long E) {
    __shared__ unsigned spref[NB_SCAN];
    int t = threadIdx.x;
    if (t == 0) {
        unsigned run = 0;
        for (int k = 0; k < NB_SCAN; k++) { unsigned v = bsum[k]; spref[k] = run; run += v; }
    }
    __syncthreads();
    int i = blockIdx.x * blockDim.x + t;
    if (i < NN) {
        unsigned dg = deg[i];
        unsigned incl = part[i] + spref[i >> 10];
        unsigned excl = incl - (dg - 1u);
        off[i] = excl;
        curs[i] = excl;
        dis[i] = rsqrtf((float)dg);
    }
    if (i == 0) off[NN] = (unsigned)E;
}

__global__ void k_place(const void* __restrict__ ei, long long E,
                        const float* __restrict__ dis, unsigned* __restrict__ curs,
                        int2* __restrict__ edges) {
    long long i = ((long long)blockIdx.x * blockDim.x + threadIdx.x) * 2;
    if (i >= E) return;
    int s0, d0, s1 = -1, d1 = -1;
    if (g_is64) {
        const long long* ps = (const long long*)ei;
        const long long* pd = ps + E;
        s0 = (int)__ldcs(&ps[i]);
        d0 = (int)__ldcs(&pd[i]);
        if (i + 1 < E) { s1 = (int)__ldcs(&ps[i + 1]); d1 = (int)__ldcs(&pd[i + 1]); }
    } else {
        const int* ps = (const int*)ei;
        const int* pd = ps + E;
        s0 = __ldcs(&ps[i]);
        d0 = __ldcs(&pd[i]);
        if (i + 1 < E) { s1 = __ldcs(&ps[i + 1]); d1 = __ldcs(&pd[i + 1]); }
    }
    {
        unsigned pos = atomicAdd(&curs[d0], 1u);
        float nrm = dis[s0] * dis[d0];
        edges[pos] = make_int2(s0, __float_as_int(nrm));
    }
    if (s1 >= 0) {
        unsigned pos = atomicAdd(&curs[d1], 1u);
        float nrm = dis[s1] * dis[d1];
        edges[pos] = make_int2(s1, __float_as_int(nrm));
    }
}

// ---------------- bf16 split-3 HMMA GEMM: out = hin @ W^T ----------------
// IN16: A input is fp16 (g_h); else fp32. Split-3 on fp16 input is exact.
template <int NT, bool HEAD, bool IN16>
__global__ __launch_bounds__(256) void k_mm(
    const void* __restrict__ hinv, const uint4* __restrict__ frag,
    const float* __restrict__ bias, void* __restrict__ outv, int base)
{
    extern __shared__ char smem[];
    constexpr int APL = 128 * KP * 2;            // one A plane (bytes)
    const int AH = 0, AL = APL;
    constexpr int WN = NT / 2;
    constexpr int NTI = WN / 8;
    constexpr int NT8 = NT / 8;

    const uint32_t sb = smem_u32(smem);
    const int t = threadIdx.x;
    const int w = t >> 5, lane = t & 31;
    const int node0 = base + blockIdx.x * 128;

    #pragma unroll
    for (int idx = t; idx < 128 * 32; idx += 256) {
        int row = idx >> 5, kq = idx & 31;
        int node = node0 + row;
        float4 v = make_float4(0.f, 0.f, 0.f, 0.f);
        if (node < NN) {
            if (IN16) {
                const __half* hp = (const __half*)hinv;
                uint2 raw = *(const uint2*)(hp + (size_t)node * 128 + kq * 4);
                float2 f01 = __half22float2(*(__half2*)&raw.x);
                float2 f23 = __half22float2(*(__half2*)&raw.y);
                v = make_float4(f01.x, f01.y, f23.x, f23.y);
            } else {
                v = __ldg((const float4*)((const float*)hinv + (size_t)node * 128 + kq * 4));
            }
        }
        uint2 hi, lo;
        split4(v, hi, lo);
        int boff = (row * KP + kq * 4) * 2;
        *(uint2*)(smem + AH + boff) = hi;
        *(uint2*)(smem + AL + boff) = lo;
    }
    __syncthreads();

    const int wm = w >> 1, wn = w & 1;
    float acc[2][NTI][4];
    #pragma unroll
    for (int mi = 0; mi < 2; mi++)
        #pragma unroll
        for (int ni = 0; ni < NTI; ni++)
            #pragma unroll
            for (int j = 0; j < 4; j++) acc[mi][ni][j] = 0.f;

    const int tl = lane >> 3, r8 = lane & 7;
    const uint32_t arow = (uint32_t)((wm * 32 + (tl & 1) * 8 + r8) * KP + (tl >> 1) * 8) * 2;

    #pragma unroll
    for (int ks = 0; ks < 8; ks++) {
        const uint32_t kof = (uint32_t)(ks * 16) * 2;
        uint32_t ah[2][4], al[2][4];
        #pragma unroll
        for (int mi = 0; mi < 2; mi++) {
            uint32_t ad = sb + arow + (uint32_t)(mi * 16 * KP) * 2 + kof;
            ldsm_x4(ah[mi], ad + AH);
            ldsm_x4(al[mi], ad + AL);
        }
        #pragma unroll
        for (int ni = 0; ni < NTI; ni++) {
            uint4 f = __ldg(&frag[(size_t)((ks * NT8 + wn * NTI + ni) * 32 + lane)]);
            uint32_t bh[2] = {f.x, f.y};
            uint32_t bl[2] = {f.z, f.w};
            #pragma unroll
            for (int mi = 0; mi < 2; mi++) {
                mma_bf16(acc[mi][ni], ah[mi], bh);
                mma_bf16(acc[mi][ni], ah[mi], bl);
                mma_bf16(acc[mi][ni], al[mi], bh);
            }
        }
    }

    const int g = lane >> 2, tg = lane & 3;
    #pragma unroll
    for (int mi = 0; mi < 2; mi++) {
        int rb = node0 + wm * 32 + mi * 16;
        #pragma unroll
        for (int ni = 0; ni < NTI; ni++) {
            int col = wn * WN + ni * 8 + tg * 2;
            int n1 = rb + g, n2 = rb + g + 8;
            if (HEAD) {
                float2 c01 = make_float2(acc[mi][ni][0], acc[mi][ni][1]);
                float2 c23 = make_float2(acc[mi][ni][2], acc[mi][ni][3]);
                float2 bb = *(const float2*)(bias + col);
                c01.x += bb.x; c01.y += bb.y;
                c23.x += bb.x; c23.y += bb.y;
                float* out = (float*)outv;
                if (n1 < NN) *(float2*)(out + (size_t)n1 * NT + col) = c01;
                if (n2 < NN) *(float2*)(out + (size_t)n2 * NT + col) = c23;
            } else {
                __half* out = (__half*)outv;
                __half2 p01 = __floats2half2_rn(acc[mi][ni][0], acc[mi][ni][1]);
                __half2 p23 = __floats2half2_rn(acc[mi][ni][2], acc[mi][ni][3]);
                if (n1 < NN) *(__half2*)(out + (size_t)n1 * DH + col) = p01;
                if (n2 < NN) *(__half2*)(out + (size_t)n2 * DH + col) = p23;
            }
        }
    }
}

// ---------------- fused aggregate + epilogue (fp16 m + fp16 h out) -------
// RES16: residual is fp16 (g_h, layer 2); else fp32 stream (x, evict-first).
template <bool RES16>
__global__ __launch_bounds__(128) void k_aggr(
    const int2* __restrict__ edges, const unsigned* __restrict__ off,
    const float* __restrict__ dis, const __half* __restrict__ m,
    const float* __restrict__ bias, const void* __restrict__ resv,
    __half* __restrict__ ho, int base)
{
    int node = base + blockIdx.x * 4 + (threadIdx.x >> 5);
    if (node >= NN) return;
    const int lane = threadIdx.x & 31;
    const int hf = lane >> 4;                 // half-warp id
    const int l16 = lane & 15;
    const int co = l16 * 8;                   // column offset (8 halfs = 16B)

    unsigned e0 = off[node];
    unsigned cnt = off[node + 1] - e0;
    unsigned mA = (cnt + 1) >> 1;             // edges in half 0
    unsigned myCnt = hf ? (cnt - mA) : mA;
    const int2* ep = edges + e0 + (hf ? mA : 0);

    float d = dis[node];
    float sd = hf ? 0.f : (d * d);            // self term only on half 0

    float a0[8], a1[8];
    #pragma unroll
    for (int j = 0; j < 8; j++) { a0[j] = 0.f; a1[j] = 0.f; }

    {
        uint4 mw = *(const uint4*)(m + (size_t)node * DH + co);
        acc8(a0, mw, sd);
    }

    unsigned k = 0;
    for (; k + 2 <= myCnt; k += 2) {
        int2 ea = __ldcs(&ep[k]);
        int2 eb = __ldcs(&ep[k + 1]);
        uint4 va = *(const uint4*)(m + (size_t)ea.x * DH + co);
        uint4 vb = *(const uint4*)(m + (size_t)eb.x * DH + co);
        acc8(a0, va, __int_as_float(ea.y));
        acc8(a1, vb, __int_as_float(eb.y));
    }
    if (k < myCnt) {
        int2 ea = __ldcs(&ep[k]);
        uint4 va = *(const uint4*)(m + (size_t)ea.x * DH + co);
        acc8(a0, va, __int_as_float(ea.y));
    }

    float r[8];
    #pragma unroll
    for (int j = 0; j < 8; j++) r[j] = a0[j] + a1[j];
    #pragma unroll
    for (int j = 0; j < 8; j++) r[j] += __shfl_xor_sync(~0u, r[j], 16);

    if (hf == 0) {
        float4 b0 = __ldg(&((const float4*)bias)[l16 * 2]);
        float4 b1 = __ldg(&((const float4*)bias)[l16 * 2 + 1]);
        float rs[8];
        if (RES16) {
            const __half* rp = (const __half*)resv;
            uint4 rw = *(const uint4*)(rp + (size_t)node * DH + co);
            float2 q0 = __half22float2(*(__half2*)&rw.x);
            float2 q1 = __half22float2(*(__half2*)&rw.y);
            float2 q2 = __half22float2(*(__half2*)&rw.z);
            float2 q3 = __half22float2(*(__half2*)&rw.w);
            rs[0] = q0.x; rs[1] = q0.y; rs[2] = q1.x; rs[3] = q1.y;
            rs[4] = q2.x; rs[5] = q2.y; rs[6] = q3.x; rs[7] = q3.y;
        } else {
            const float4* rr = (const float4*)((const float*)resv + (size_t)node * DH + co);
            float4 r0 = __ldcs(&rr[0]);
            float4 r1 = __ldcs(&rr[1]);
            rs[0] = r0.x; rs[1] = r0.y; rs[2] = r0.z; rs[3] = r0.w;
            rs[4] = r1.x; rs[5] = r1.y; rs[6] = r1.z; rs[7] = r1.w;
        }
        float o[8];
        o[0] = fmaxf(r[0] + b0.x, 0.f) + rs[0];
        o[1] = fmaxf(r[1] + b0.y, 0.f) + rs[1];
        o[2] = fmaxf(r[2] + b0.z, 0.f) + rs[2];
        o[3] = fmaxf(r[3] + b0.w, 0.f) + rs[3];
        o[4] = fmaxf(r[4] + b1.x, 0.f) + rs[4];
        o[5] = fmaxf(r[5] + b1.y, 0.f) + rs[5];
        o[6] = fmaxf(r[6] + b1.z, 0.f) + rs[6];
        o[7] = fmaxf(r[7] + b1.w, 0.f) + rs[7];
        __half2 q0 = __floats2half2_rn(o[0], o[1]);
        __half2 q1 = __floats2half2_rn(o[2], o[3]);
        __half2 q2 = __floats2half2_rn(o[4], o[5]);
        __half2 q3 = __floats2half2_rn(o[6], o[7]);
        uint4 ow = make_uint4(*(uint32_t*)&q0, *(uint32_t*)&q1,
                              *(uint32_t*)&q2, *(uint32_t*)&q3);
        *(uint4*)(ho + (size_t)node * DH + co) = ow;
    }
}

// ---------------- launch (forked-graph DAG, chunk-pipelined tail) --------
extern "C" void kernel_launch(void* const* d_in, const int* in_sizes, int n_in,
                              void* d_out, int out_size) {
    const float* x  = (const float*)d_in[0];
    const void*  ei = d_in[1];
    const float* W1 = (const float*)d_in[2];
    const float* b1 = (const float*)d_in[3];
    const float* W2 = (const float*)d_in[4];
    const float* b2 = (const float*)d_in[5];
    const float* Wl = (const float*)d_in[6];
    const float* bl = (const float*)d_in[7];
    long long E = (long long)in_sizes[1] / 2;

    __half *m1, *m2, *h;
    float *dis;
    unsigned *deg, *part, *bsum, *off, *curs;
    int2* edges;
    uint4 *wf1, *wf2, *wfl;
    cudaGetSymbolAddress((void**)&m1,    g_m1);
    cudaGetSymbolAddress((void**)&m2,    g_m2);
    cudaGetSymbolAddress((void**)&h,     g_h);
    cudaGetSymbolAddress((void**)&dis,   g_dis);
    cudaGetSymbolAddress((void**)&deg,   g_deg);
    cudaGetSymbolAddress((void**)&part,  g_part);
    cudaGetSymbolAddress((void**)&bsum,  g_bsum);
    cudaGetSymbolAddress((void**)&off,   g_off);
    cudaGetSymbolAddress((void**)&curs,  g_curs);
    cudaGetSymbolAddress((void**)&edges, g_edge);
    cudaGetSymbolAddress((void**)&wf1,   g_wf1);
    cudaGetSymbolAddress((void**)&wf2,   g_wf2);
    cudaGetSymbolAddress((void**)&wfl,   g_wfl);

    const int SMEM_MM = 2 * (128 * KP * 2);      // 69632 (A planes only)
    cudaFuncSetAttribute(k_mm<DH, false, false>, cudaFuncAttributeMaxDynamicSharedMemorySize, SMEM_MM);
    cudaFuncSetAttribute(k_mm<DH, false, true>,  cudaFuncAttributeMaxDynamicSharedMemorySize, SMEM_MM);
    cudaFuncSetAttribute(k_mm<CC, true, true>,   cudaFuncAttributeMaxDynamicSharedMemorySize, SMEM_MM);

    cudaStream_t s2;
    cudaStreamCreateWithFlags(&s2, cudaStreamNonBlocking);
    cudaEvent_t evP, evM1, evH0, evH1, evM2a, evM2b, evG0, evG1, evD;
    cudaEventCreateWithFlags(&evP,   cudaEventDisableTiming);
    cudaEventCreateWithFlags(&evM1,  cudaEventDisableTiming);
    cudaEventCreateWithFlags(&evH0,  cudaEventDisableTiming);
    cudaEventCreateWithFlags(&evH1,  cudaEventDisableTiming);
    cudaEventCreateWithFlags(&evM2a, cudaEventDisableTiming);
    cudaEventCreateWithFlags(&evM2b, cudaEventDisableTiming);
    cudaEventCreateWithFlags(&evG0,  cudaEventDisableTiming);
    cudaEventCreateWithFlags(&evG1,  cudaEventDisableTiming);
    cudaEventCreateWithFlags(&evD,   cudaEventDisableTiming);

    const unsigned dblocks = (unsigned)(((E + 1) / 2 + 255) / 256);
    const int MB = 391;                         // gemm blocks per chunk
    const int AB0 = CHUNK / 4;                  // 128-thd aggr blocks (4 nodes)
    const int AB1 = (NN - CHUNK + 3) / 4;

    // prologue shared by both branches (deg init + detect + W fragments)
    k_pre<<<(NN + 255) / 256, 256>>>((const int*)ei, deg, W1, W2, Wl, wf1, wf2, wfl);
    cudaEventRecord(evP, 0);
    cudaStreamWaitEvent(s2, evP, 0);

    // ---- branch B (s2): GEMM1 ----
    k_mm<DH, false, false><<<2 * MB, 256, SMEM_MM, s2>>>(x, wf1, nullptr, m1, 0);
    cudaEventRecord(evM1, s2);

    // ---- branch A (stream 0): CSR build ----
    k_deg<<<dblocks, 256>>>(ei, E, deg);
    k_scan1<<<NB_SCAN, 1024>>>(deg, part, bsum);
    k_scan3<<<(NN + 255) / 256, 256>>>(deg, part, bsum, off, curs, dis, E);
    k_place<<<dblocks, 256>>>(ei, E, dis, curs, edges);

    // ---- join for aggr1, pipeline layer boundaries ----
    cudaStreamWaitEvent(0, evM1, 0);
    k_aggr<false><<<AB0, 128>>>(edges, off, dis, m1, b1, x, h, 0);
    cudaEventRecord(evH0, 0);
    k_aggr<false><<<AB1, 128>>>(edges, off, dis, m1, b1, x, h, CHUNK);
    cudaEventRecord(evH1, 0);

    cudaStreamWaitEvent(s2, evH0, 0);
    k_mm<DH, false, true><<<MB, 256, SMEM_MM, s2>>>(h, wf2, nullptr, m2, 0);
    cudaEventRecord(evM2a, s2);
    cudaStreamWaitEvent(s2, evH1, 0);
    k_mm<DH, false, true><<<MB, 256, SMEM_MM, s2>>>(h, wf2, nullptr, m2, CHUNK);
    cudaEventRecord(evM2b, s2);

    cudaStreamWaitEvent(0, evM2a, 0);
    cudaStreamWaitEvent(0, evM2b, 0);
    k_aggr<true><<<AB0, 128>>>(edges, off, dis, m2, b2, h, h, 0);
    cudaEventRecord(evG0, 0);
    k_aggr<true><<<AB1, 128>>>(edges, off, dis, m2, b2, h, h, CHUNK);
    cudaEventRecord(evG1, 0);

    cudaStreamWaitEvent(s2, evG0, 0);
    k_mm<CC, true, true><<<MB, 256, SMEM_MM, s2>>>(h, wfl, bl, d_out, 0);
    cudaStreamWaitEvent(s2, evG1, 0);
    k_mm<CC, true, true><<<MB, 256, SMEM_MM, s2>>>(h, wfl, bl, d_out, CHUNK);
    cudaEventRecord(evD, s2);

    // join back into origin stream (required for capture)
    cudaStreamWaitEvent(0, evD, 0);
}